// round 16
// baseline (speedup 1.0000x reference)
#include <cuda_runtime.h>
#include <cuda_bf16.h>

// TimeWarp, single fused kernel.
// R14 shape (TILE_J=256, full 128-row tiles, grid 1024, __stcs) with 512-thread
// blocks: SM occupancy saturates at 4 resident blocks, setup phase runs 2x wider.
// Register-resident y-tables, single barrier.
// B=32, F=128, T=8192, fp32.

#define NB 32
#define NF 128
#define NT 8192
#define TILE_J   256              // j's per block
#define TILE_C   (TILE_J / 4)     // 64 float4-chunks per block
#define MAX_ROWS 12               // y-span over 256 j's <= ~4.1 (+2 lerp +1) -> <=8; 12 safe
#define NTHR     512

__global__ __launch_bounds__(NTHR, 4)
void timewarp_fused(const float* __restrict__ S,
                    const int*   __restrict__ psrc,
                    const int*   __restrict__ pdst,
                    float*       __restrict__ out)
{
    __shared__ float sP[MAX_ROWS * NF];        // x-resampled rows [Ymin..), full i range

    const int t  = threadIdx.x;                // 512 threads
    const int jt = blockIdx.x;                 // 0..31  j-tile
    const int b  = blockIdx.y;                 // 0..31  batch
    const int j_base = jt * TILE_J;

    const float s = (float)__ldg(psrc);
    const float d = (float)__ldg(pdst);
    const float rl = s / d;
    const float rr = ((float)NT - s) / ((float)NT - d);

    // y(j) exactly as the reference (monotone nondecreasing in j)
    auto yval = [&](float tf) -> float {
        float idx = (tf < d) ? (tf * rl) : fmaf(tf - d, rr, s);
        idx = fminf(fmaxf(idx, 0.0f), (float)(NT - 1));
        float y = idx * (1.0f / (float)(NT - 1)) * (float)(NF - 1);
        return fminf(fmaxf(y, 0.0f), (float)(NF - 1));
    };

    // Tile row window (computed redundantly per thread; no smem, no barrier)
    const int Ymin = (int)floorf(yval((float)j_base));
    int nrows = (int)floorf(yval((float)(j_base + TILE_J - 1))) + 3 - Ymin;
    if (nrows > MAX_ROWS) nrows = MAX_ROWS;

    // ---------- build P-tile: x-resample needed rows, all 128 i ----------
    const float* Sb = S + (size_t)b * (size_t)(NF * NT);
    for (int v = t; v < nrows * NF; v += NTHR) {      // nrows<=8 -> <=2 iters/thread
        const int r  = v >> 7;
        const int i  = v & (NF - 1);
        const int rs = min(Ymin + r, NF - 1);         // border clamp / pad rows

        float x_pix = ((float)i / (float)(NF - 1)) * (float)(NT - 1);
        x_pix = fminf(fmaxf(x_pix, 0.0f), (float)(NT - 1));
        const float x0f = floorf(x_pix);
        const int   x0  = (int)x0f;
        const int   x1  = min(x0 + 1, NT - 1);
        const float wx  = x_pix - x0f;

        const float* row = Sb + (size_t)rs * NT;
        const float v0 = __ldg(row + x0);
        const float v1 = __ldg(row + x1);
        sP[v] = fmaf(wx, v1 - v0, v0);
    }
    __syncthreads();                                  // the only barrier

    // ---------- stream all 128 freq rows x 256 j ----------
    const int tx = t & (TILE_C - 1);                  // chunk within tile (warp-contiguous)
    const int ty = t >> 6;                            // i-offset 0..7

    // Register-resident per-chunk y tables (identical FP sequence to prior rounds)
    float wy0, wy1, wy2, wy3; int Y;
    {
        float y  = yval((float)(j_base + tx * 4));
        float yf = floorf(y);
        wy0 = y - yf;  Y = (int)yf;
        y = yval((float)(j_base + tx * 4 + 1)); wy1 = y - floorf(y);
        y = yval((float)(j_base + tx * 4 + 2)); wy2 = y - floorf(y);
        y = yval((float)(j_base + tx * 4 + 3)); wy3 = y - floorf(y);
    }
    const int rel = Y - Ymin;                         // 0..nrows-3
    const float* pc = sP + rel * NF;

    const bool s1 = wy1 < wy0;                        // floor advanced <=> frac wrapped
    const bool s2 = wy2 < wy0;
    const bool s3 = wy3 < wy0;

    float* obase = out + ((size_t)b * NF) * (size_t)NT + (size_t)(j_base + tx * 4);

#pragma unroll 8
    for (int r = 0; r < NF / 8; r++) {                // 16 iterations
        const int i = r * 8 + ty;

        const float pA = pc[i];
        const float pB = pc[NF + i];
        const float pC = pc[2 * NF + i];

        float o0 = fmaf(wy0, pB - pA, pA);
        float l1 = s1 ? pB : pA, h1 = s1 ? pC : pB;
        float l2 = s2 ? pB : pA, h2 = s2 ? pC : pB;
        float l3 = s3 ? pB : pA, h3 = s3 ? pC : pB;
        float o1 = fmaf(wy1, h1 - l1, l1);
        float o2 = fmaf(wy2, h2 - l2, l2);
        float o3 = fmaf(wy3, h3 - l3, l3);

        __stcs(reinterpret_cast<float4*>(obase + (size_t)i * NT),
               make_float4(o0, o1, o2, o3));
    }
}

extern "C" void kernel_launch(void* const* d_in, const int* in_sizes, int n_in,
                              void* d_out, int out_size)
{
    const float* S    = (const float*)d_in[0];
    const int*   psrc = (const int*)d_in[1];
    const int*   pdst = (const int*)d_in[2];
    float*       out  = (float*)d_out;

    dim3 grid(NT / TILE_J, NB);                       // 32 x 32 = 1024 blocks
    timewarp_fused<<<grid, NTHR>>>(S, psrc, pdst, out);
}

// round 17
// speedup vs baseline: 1.1096x; 1.1096x over previous
#include <cuda_runtime.h>
#include <cuda_bf16.h>

// TimeWarp, single fused kernel — converged configuration (R14) + bank-conflict-free sP.
// Block = (b, j-tile of 256) covering all 128 freq rows; grid 1024 x 256 threads.
// Register-resident y-tables, single barrier, __stcs streaming stores.
// sP row stride padded 128 -> 132 floats so lanes with different floor(y) rows
// hit different banks (512B same-bank stride -> 528B, +4 banks per row step).
// B=32, F=128, T=8192, fp32.

#define NB 32
#define NF 128
#define NT 8192
#define TILE_J   256              // j's per block
#define TILE_C   (TILE_J / 4)     // 64 float4-chunks per block
#define MAX_ROWS 12               // y-span over 256 j's <= ~4.1 (+2 lerp +1) -> <=8; 12 safe
#define PSTR     132              // padded sP row stride (kills LDS bank conflicts)

__global__ __launch_bounds__(256, 8)
void timewarp_fused(const float* __restrict__ S,
                    const int*   __restrict__ psrc,
                    const int*   __restrict__ pdst,
                    float*       __restrict__ out)
{
    __shared__ float sP[MAX_ROWS * PSTR];      // x-resampled rows [Ymin..), padded stride

    const int t  = threadIdx.x;                // 256 threads
    const int jt = blockIdx.x;                 // 0..31  j-tile
    const int b  = blockIdx.y;                 // 0..31  batch
    const int j_base = jt * TILE_J;

    const float s = (float)__ldg(psrc);
    const float d = (float)__ldg(pdst);
    const float rl = s / d;
    const float rr = ((float)NT - s) / ((float)NT - d);

    // y(j) exactly as the reference (monotone nondecreasing in j)
    auto yval = [&](float tf) -> float {
        float idx = (tf < d) ? (tf * rl) : fmaf(tf - d, rr, s);
        idx = fminf(fmaxf(idx, 0.0f), (float)(NT - 1));
        float y = idx * (1.0f / (float)(NT - 1)) * (float)(NF - 1);
        return fminf(fmaxf(y, 0.0f), (float)(NF - 1));
    };

    // Tile row window (computed redundantly per thread; no smem, no barrier)
    const int Ymin = (int)floorf(yval((float)j_base));
    int nrows = (int)floorf(yval((float)(j_base + TILE_J - 1))) + 3 - Ymin;
    if (nrows > MAX_ROWS) nrows = MAX_ROWS;

    // ---------- build P-tile: x-resample needed rows, all 128 i ----------
    const float* Sb = S + (size_t)b * (size_t)(NF * NT);
    for (int v = t; v < nrows * NF; v += 256) {       // nrows<=8 -> <=4 iters/thread
        const int r  = v >> 7;
        const int i  = v & (NF - 1);
        const int rs = min(Ymin + r, NF - 1);         // border clamp / pad rows

        float x_pix = ((float)i / (float)(NF - 1)) * (float)(NT - 1);
        x_pix = fminf(fmaxf(x_pix, 0.0f), (float)(NT - 1));
        const float x0f = floorf(x_pix);
        const int   x0  = (int)x0f;
        const int   x1  = min(x0 + 1, NT - 1);
        const float wx  = x_pix - x0f;

        const float* row = Sb + (size_t)rs * NT;
        const float v0 = __ldg(row + x0);
        const float v1 = __ldg(row + x1);
        sP[r * PSTR + i] = fmaf(wx, v1 - v0, v0);
    }
    __syncthreads();                                  // the only barrier

    // ---------- stream all 128 freq rows x 256 j ----------
    const int tx = t & (TILE_C - 1);                  // chunk within tile (warp-contiguous)
    const int ty = t >> 6;                            // i-offset 0..3

    // Register-resident per-chunk y tables (identical FP sequence to prior rounds)
    float wy0, wy1, wy2, wy3; int Y;
    {
        float y  = yval((float)(j_base + tx * 4));
        float yf = floorf(y);
        wy0 = y - yf;  Y = (int)yf;
        y = yval((float)(j_base + tx * 4 + 1)); wy1 = y - floorf(y);
        y = yval((float)(j_base + tx * 4 + 2)); wy2 = y - floorf(y);
        y = yval((float)(j_base + tx * 4 + 3)); wy3 = y - floorf(y);
    }
    const int rel = Y - Ymin;                         // 0..nrows-3
    const float* pc = sP + rel * PSTR;

    const bool s1 = wy1 < wy0;                        // floor advanced <=> frac wrapped
    const bool s2 = wy2 < wy0;
    const bool s3 = wy3 < wy0;

    float* obase = out + ((size_t)b * NF) * (size_t)NT + (size_t)(j_base + tx * 4);

#pragma unroll 8
    for (int r = 0; r < NF / 4; r++) {                // 32 iterations
        const int i = r * 4 + ty;

        const float pA = pc[i];
        const float pB = pc[PSTR + i];
        const float pC = pc[2 * PSTR + i];

        float o0 = fmaf(wy0, pB - pA, pA);
        float l1 = s1 ? pB : pA, h1 = s1 ? pC : pB;
        float l2 = s2 ? pB : pA, h2 = s2 ? pC : pB;
        float l3 = s3 ? pB : pA, h3 = s3 ? pC : pB;
        float o1 = fmaf(wy1, h1 - l1, l1);
        float o2 = fmaf(wy2, h2 - l2, l2);
        float o3 = fmaf(wy3, h3 - l3, l3);

        __stcs(reinterpret_cast<float4*>(obase + (size_t)i * NT),
               make_float4(o0, o1, o2, o3));
    }
}

extern "C" void kernel_launch(void* const* d_in, const int* in_sizes, int n_in,
                              void* d_out, int out_size)
{
    const float* S    = (const float*)d_in[0];
    const int*   psrc = (const int*)d_in[1];
    const int*   pdst = (const int*)d_in[2];
    float*       out  = (float*)d_out;

    dim3 grid(NT / TILE_J, NB);                       // 32 x 32 = 1024 blocks
    timewarp_fused<<<grid, 256>>>(S, psrc, pdst, out);
}